// round 1
// baseline (speedup 1.0000x reference)
#include <cuda_runtime.h>
#include <math.h>

#define W_IMG 2048
#define H_IMG 2048
#define NPIX (W_IMG * H_IMG)

// scratch (no cudaMalloc allowed)
__device__ float g_scat[NPIX];   // scatterer, [h][w]
__device__ float g_tmp[NPIX];    // after horizontal conv, [h][w]
__device__ float g_ax[24];       // 23 axial taps (normalized) + zero pad
__device__ float g_lat[64];      // 61 lateral taps (normalized) + zero pad

#define DB_SCALE 8.6858896380650365530225783783321f  // 20/ln(10)

// ---------------------------------------------------------------------------
// Kernel 0: compute separable PSF taps from the scalar jitters (device-side,
// since rand_ax/rand_lat live in device memory and we are graph-captured).
// ---------------------------------------------------------------------------
__global__ void k_weights(const float* __restrict__ ra_p,
                          const float* __restrict__ rl_p) {
    __shared__ float s_ax[23];
    __shared__ float s_lat[61];
    int t = threadIdx.x;
    float ra = ra_p[0];
    float rl = rl_p[0];

    const double HALF_AX  = 3.08e-4;          // TONE_LENGTH/2
    const double HALF_LAT = 6.16e-4;          // F*WL*2
    const double SH = 0.05 / 2048.0;
    const double SW = 0.04 / 2048.0;
    const double TONE = 6.16e-4;
    const double FWL  = 3.08e-4;              // F_NUMBER * WAVELENGTH
    const double PI = 3.14159265358979323846;

    if (t < 23) {
        double p = (double)(t - 11) / 11.0 * HALF_AX + (double)ra * SH;
        double arg = 3.0 * (2.0 / TONE) * p;
        s_ax[t] = (float)exp(-0.5 * arg * arg);
    }
    if (t < 61) {
        double q = ((double)(t - 30) / 30.0 * HALF_LAT + (double)rl * SW) / FWL;
        double x = PI * q;
        double si = (fabs(x) < 1e-12) ? 1.0 : sin(x) / x;
        s_lat[t] = (float)(si * si);
    }
    __syncthreads();
    if (t == 0) {
        float sa = 0.f, sl = 0.f;
        for (int i = 0; i < 23; i++) sa += s_ax[i];
        for (int j = 0; j < 61; j++) sl += s_lat[j];
        float inv_sa = 1.0f / sa;
        float inv_sl = 1.0f / sl;
        for (int i = 0; i < 23; i++) g_ax[i] = s_ax[i] * inv_sa;
        g_ax[23] = 0.f;
        for (int j = 0; j < 61; j++) g_lat[j] = s_lat[j] * inv_sl;
        for (int j = 61; j < 64; j++) g_lat[j] = 0.f;
    }
}

// ---------------------------------------------------------------------------
// Kernel 1: scatterer = exp(raw[...,0]).T  (smem-tiled transpose), also emits
// scatterers_map = 20*log10(scatterer+1).
// raw element (w,h,0) at index (w*H + h)*4.
// ---------------------------------------------------------------------------
__global__ void __launch_bounds__(256)
k_exp_transpose(const float* __restrict__ raw, float* __restrict__ scatmap) {
    __shared__ float tile[32][33];
    int w0 = blockIdx.x * 32;
    int h0 = blockIdx.y * 32;
    int tx = threadIdx.x, ty = threadIdx.y;

#pragma unroll
    for (int k = 0; k < 4; k++) {
        int w = w0 + ty + k * 8;
        int h = h0 + tx;
        float v = raw[((size_t)w * H_IMG + h) * 4];
        tile[tx][ty + k * 8] = __expf(v);   // tile[h_local][w_local]
    }
    __syncthreads();
#pragma unroll
    for (int k = 0; k < 4; k++) {
        int h = h0 + ty + k * 8;
        int w = w0 + tx;
        float s = tile[ty + k * 8][tx];
        g_scat[h * W_IMG + w]  = s;
        scatmap[h * W_IMG + w] = DB_SCALE * log1pf(s);
    }
}

// ---------------------------------------------------------------------------
// Kernel 2: horizontal 61-tap conv with reflect padding, 4 outputs/thread via
// float4 sliding window (taps zero-padded to 64).
// Block: 128 threads -> 512 outputs on one row. Grid: (4, 2048).
// ---------------------------------------------------------------------------
__global__ void __launch_bounds__(128)
k_hconv() {
    __shared__ __align__(16) float s[576];
    __shared__ float sw[64];
    int y  = blockIdx.y;
    int X0 = blockIdx.x * 512;
    int t  = threadIdx.x;

    if (t < 64) sw[t] = g_lat[t];

    const float* row = g_scat + y * W_IMG;
    for (int p = t; p < 576; p += 128) {
        int x = X0 - 30 + p;
        x = (x < 0) ? -x : ((x >= W_IMG) ? 2 * W_IMG - 2 - x : x);
        s[p] = row[x];
    }
    __syncthreads();

    const float4* s4 = (const float4*)s;
    float4 lo = s4[t];
    float a0 = 0.f, a1 = 0.f, a2 = 0.f, a3 = 0.f;
#pragma unroll
    for (int a = 0; a < 16; a++) {
        float4 hi = s4[t + a + 1];
        float c0 = sw[4 * a + 0], c1 = sw[4 * a + 1];
        float c2 = sw[4 * a + 2], c3 = sw[4 * a + 3];
        a0 += c0 * lo.x + c1 * lo.y + c2 * lo.z + c3 * lo.w;
        a1 += c0 * lo.y + c1 * lo.z + c2 * lo.w + c3 * hi.x;
        a2 += c0 * lo.z + c1 * lo.w + c2 * hi.x + c3 * hi.y;
        a3 += c0 * lo.w + c1 * hi.x + c2 * hi.y + c3 * hi.z;
        lo = hi;
    }
    float4 out = make_float4(a0, a1, a2, a3);
    ((float4*)(g_tmp + y * W_IMG + X0))[t] = out;
}

// ---------------------------------------------------------------------------
// Kernel 3: vertical 23-tap conv with reflect padding + b_mode epilogue.
// Tile: 32 (x) x 128 (y) outputs per block; block (32,8); each thread does
// 16 outputs as 4 register-sliding groups of 4.
// ---------------------------------------------------------------------------
__global__ void __launch_bounds__(256)
k_vconv(float* __restrict__ bmode, float* __restrict__ env) {
    __shared__ float tile[152 * 32];
    __shared__ float sax[24];
    int x0 = blockIdx.x * 32;
    int y0 = blockIdx.y * 128;
    int tx = threadIdx.x, ty = threadIdx.y;
    int tid = ty * 32 + tx;

    if (tid < 24) sax[tid] = g_ax[tid];

    for (int idx = tid; idx < 152 * 32; idx += 256) {
        int p = idx >> 5;
        int c = idx & 31;
        int y = y0 - 11 + p;
        y = (y < 0) ? -y : ((y >= H_IMG) ? 2 * H_IMG - 2 - y : y);
        tile[idx] = g_tmp[y * W_IMG + x0 + c];
    }
    __syncthreads();

#pragma unroll
    for (int g = 0; g < 4; g++) {
        int yb = ty * 16 + g * 4;          // local row of first output in group
        const float* col = tile + yb * 32 + tx;
        float v0 = col[0], v1 = col[32], v2 = col[64], v3 = col[96];
        float a0 = 0.f, a1 = 0.f, a2 = 0.f, a3 = 0.f;
#pragma unroll
        for (int i = 0; i < 23; i++) {
            float c = sax[i];
            a0 += c * v0; a1 += c * v1; a2 += c * v2; a3 += c * v3;
            v0 = v1; v1 = v2; v2 = v3;
            v3 = col[(i + 4) * 32];        // max row yb+26 <= 150 < 152, safe
        }
        int yg = y0 + yb;
        float acc[4] = {a0, a1, a2, a3};
#pragma unroll
        for (int k = 0; k < 4; k++) {
            int o = (yg + k) * W_IMG + x0 + tx;
            env[o]   = acc[k];
            bmode[o] = DB_SCALE * log1pf(acc[k]);
        }
    }
}

// ---------------------------------------------------------------------------
extern "C" void kernel_launch(void* const* d_in, const int* in_sizes, int n_in,
                              void* d_out, int out_size) {
    const float* raw = (const float*)d_in[0];
    const float* ra  = (const float*)d_in[1];
    const float* rl  = (const float*)d_in[2];
    float* out     = (float*)d_out;
    float* bmode   = out;                 // [1,1,H,W]
    float* scatmap = out + NPIX;          // [1,1,H,W]
    float* env     = out + 2 * NPIX;      // [1,1,H,W]

    k_weights<<<1, 64>>>(ra, rl);
    k_exp_transpose<<<dim3(64, 64), dim3(32, 8)>>>(raw, scatmap);
    k_hconv<<<dim3(4, 2048), 128>>>();
    k_vconv<<<dim3(64, 16), dim3(32, 8)>>>(bmode, env);
}

// round 3
// speedup vs baseline: 1.1594x; 1.1594x over previous
#include <cuda_runtime.h>
#include <math.h>

#define W_IMG 2048
#define H_IMG 2048
#define NPIX (W_IMG * H_IMG)

// scratch (no cudaMalloc allowed)
__device__ float  g_tmp[NPIX];     // after horizontal conv, [h][w]
__device__ float2 g_lat2[64];      // 61 lateral taps packed (c,c) + zero pad
__device__ float2 g_ax2[23];       // 23 axial taps packed (c,c)

#define DB_SCALE 8.6858896380650365530225783783321f  // 20/ln(10)

// ---- packed fp32x2 FMA (Blackwell) ------------------------------------
union F2U { float2 f; unsigned long long u; };

__device__ __forceinline__ float2 ffma2(float2 a, float2 b, float2 c) {
    F2U ua, ub, uc, ud;
    ua.f = a; ub.f = b; uc.f = c;
    asm("fma.rn.f32x2 %0, %1, %2, %3;"
        : "=l"(ud.u) : "l"(ua.u), "l"(ub.u), "l"(uc.u));
    return ud.f;
}

__device__ __forceinline__ int reflect_idx(int x, int n) {
    x = (x < 0) ? -x : x;
    return (x >= n) ? 2 * n - 2 - x : x;
}

// ---------------------------------------------------------------------------
// Kernel 0: compute separable PSF taps from the scalar jitters; each 1-D
// kernel normalized by its own sum (product == psf/sum(psf)). Writes packed
// (c,c) float2 arrays for the FFMA2 consumers.
// ---------------------------------------------------------------------------
__global__ void k_weights(const float* __restrict__ ra_p,
                          const float* __restrict__ rl_p) {
    __shared__ float s_ax[23];
    __shared__ float s_lat[61];
    int t = threadIdx.x;
    float ra = ra_p[0];
    float rl = rl_p[0];

    const double HALF_AX  = 3.08e-4;          // TONE_LENGTH/2
    const double HALF_LAT = 6.16e-4;          // F*WL*2
    const double SH = 0.05 / 2048.0;
    const double SW = 0.04 / 2048.0;
    const double TONE = 6.16e-4;
    const double FWL  = 3.08e-4;              // F_NUMBER * WAVELENGTH
    const double PI = 3.14159265358979323846;

    if (t < 23) {
        double p = (double)(t - 11) / 11.0 * HALF_AX + (double)ra * SH;
        double arg = 3.0 * (2.0 / TONE) * p;
        s_ax[t] = (float)exp(-0.5 * arg * arg);
    }
    if (t < 61) {
        double q = ((double)(t - 30) / 30.0 * HALF_LAT + (double)rl * SW) / FWL;
        double x = PI * q;
        double si = (fabs(x) < 1e-12) ? 1.0 : sin(x) / x;
        s_lat[t] = (float)(si * si);
    }
    __syncthreads();
    if (t == 0) {
        float sa = 0.f, sl = 0.f;
        for (int i = 0; i < 23; i++) sa += s_ax[i];
        for (int j = 0; j < 61; j++) sl += s_lat[j];
        float inv_sa = 1.0f / sa;
        float inv_sl = 1.0f / sl;
        for (int i = 0; i < 23; i++) {
            float c = s_ax[i] * inv_sa;
            g_ax2[i] = make_float2(c, c);
        }
        for (int j = 0; j < 64; j++) {
            float c = (j < 61) ? s_lat[j] * inv_sl : 0.f;
            g_lat2[j] = make_float2(c, c);
        }
    }
}

// ---------------------------------------------------------------------------
// Kernel 1 (fused): scatterer = exp(raw[...,0]).T, horizontal 61-tap conv
// with reflect padding -> g_tmp, and scatterers_map = 20*log10(scat+1).
// Tile: 128 (w) x 32 (h) outputs, 256 threads.
// SMEM layout: row-pairs interleaved -> s[(h>>1)*378 + w*2 + (h&1)], so a
// (row h, row h+1) pair at column w is one aligned float2 for FFMA2.
// ---------------------------------------------------------------------------
#define TW 128
#define TH 32
#define SWT 188           // TW + 60 halo
#define SROW 378          // 2*SWT padded by 2 -> conflict-free banks

__global__ void __launch_bounds__(256)
k1_fused(const float* __restrict__ raw, float* __restrict__ scatmap) {
    __shared__ float  s[16 * SROW];
    __shared__ float2 sc[64];
    int w0 = blockIdx.x * TW;
    int h0 = blockIdx.y * TH;
    int tid = threadIdx.x;

    if (tid < 64) sc[tid] = g_lat2[tid];

    // load + exp (transpose is implicit via indexing): lanes run along h
    for (int i = tid; i < SWT * TH; i += 256) {
        int p = i >> 5;                 // tile w index 0..187
        int h = i & 31;                 // local h
        int wg = reflect_idx(w0 + p - 30, W_IMG);
        float v = __expf(raw[((size_t)wg * H_IMG + h0 + h) * 4]);
        s[(h >> 1) * SROW + p * 2 + (h & 1)] = v;
    }
    __syncthreads();

    // compute: thread -> (h-pair h2 = tid&15, output group wg = tid>>4)
    int h2 = tid & 15;
    int wg = tid >> 4;
    const float2* rowp = (const float2*)(s + h2 * SROW);
    int base = wg * 8;

    float2 win[8], acc[8], sv[8];
#pragma unroll
    for (int j = 0; j < 8; j++) {
        win[j] = rowp[base + j];
        acc[j] = make_float2(0.f, 0.f);
    }
#pragma unroll
    for (int k = 0; k < 61; k++) {
        float2 cp = sc[k];
#pragma unroll
        for (int j = 0; j < 8; j++) acc[j] = ffma2(cp, win[j], acc[j]);
        if (k == 30) {
#pragma unroll
            for (int j = 0; j < 8; j++) sv[j] = win[j];
        }
        if (k < 60) {
#pragma unroll
            for (int j = 0; j < 7; j++) win[j] = win[j + 1];
            win[7] = rowp[base + k + 8];
        }
    }

    // stores: 2 rows x 8 cols each, as float4
    int r0 = h0 + 2 * h2;
    int c0 = w0 + base;
    float* t0 = g_tmp + (size_t)r0 * W_IMG + c0;
    float* t1 = t0 + W_IMG;
    ((float4*)t0)[0] = make_float4(acc[0].x, acc[1].x, acc[2].x, acc[3].x);
    ((float4*)t0)[1] = make_float4(acc[4].x, acc[5].x, acc[6].x, acc[7].x);
    ((float4*)t1)[0] = make_float4(acc[0].y, acc[1].y, acc[2].y, acc[3].y);
    ((float4*)t1)[1] = make_float4(acc[4].y, acc[5].y, acc[6].y, acc[7].y);

    float* m0 = scatmap + (size_t)r0 * W_IMG + c0;
    float* m1 = m0 + W_IMG;
    float l0[8], l1[8];
#pragma unroll
    for (int j = 0; j < 8; j++) {
        l0[j] = DB_SCALE * __logf(1.f + sv[j].x);
        l1[j] = DB_SCALE * __logf(1.f + sv[j].y);
    }
    ((float4*)m0)[0] = make_float4(l0[0], l0[1], l0[2], l0[3]);
    ((float4*)m0)[1] = make_float4(l0[4], l0[5], l0[6], l0[7]);
    ((float4*)m1)[0] = make_float4(l1[0], l1[1], l1[2], l1[3]);
    ((float4*)m1)[1] = make_float4(l1[4], l1[5], l1[6], l1[7]);
}

// ---------------------------------------------------------------------------
// Kernel 2: vertical 23-tap conv (reflect) + b_mode epilogue.
// Streaming, smem-free: each thread owns a column pair (float2) and 16
// output rows; 38 fully unrolled coalesced float2 loads feed 16 packed
// accumulators (transposed-FIR form).
// Threads needed: 1024 column-pairs * 128 y-strips = 131072 -> 512 blocks.
// ---------------------------------------------------------------------------
__global__ void __launch_bounds__(256)
k2_vconv(float* __restrict__ bmode, float* __restrict__ env) {
    int idx = blockIdx.x * 256 + threadIdx.x;
    int xp = idx & 1023;           // column pair
    int sy = idx >> 10;            // y strip (16 rows), 0..127
    int x  = xp * 2;
    int y0 = sy * 16;

    float2 cp[23];
#pragma unroll
    for (int i = 0; i < 23; i++) cp[i] = g_ax2[i];

    float2 acc[16];
#pragma unroll
    for (int j = 0; j < 16; j++) acc[j] = make_float2(0.f, 0.f);

#pragma unroll
    for (int r = 0; r < 38; r++) {
        int y = reflect_idx(y0 - 11 + r, H_IMG);
        float2 v = *(const float2*)(g_tmp + (size_t)y * W_IMG + x);
        int jlo = (r > 22) ? (r - 22) : 0;
        int jhi = (r < 15) ? r : 15;
#pragma unroll
        for (int j = 0; j < 16; j++) {
            if (j >= jlo && j <= jhi) acc[j] = ffma2(cp[r - j], v, acc[j]);
        }
    }

#pragma unroll
    for (int j = 0; j < 16; j++) {
        size_t o = (size_t)(y0 + j) * W_IMG + x;
        *(float2*)(env + o) = acc[j];
        float2 b = make_float2(DB_SCALE * __logf(1.f + acc[j].x),
                               DB_SCALE * __logf(1.f + acc[j].y));
        *(float2*)(bmode + o) = b;
    }
}

// ---------------------------------------------------------------------------
extern "C" void kernel_launch(void* const* d_in, const int* in_sizes, int n_in,
                              void* d_out, int out_size) {
    const float* raw = (const float*)d_in[0];
    const float* ra  = (const float*)d_in[1];
    const float* rl  = (const float*)d_in[2];
    float* out     = (float*)d_out;
    float* bmode   = out;                 // [1,1,H,W]
    float* scatmap = out + NPIX;          // [1,1,H,W]
    float* env     = out + 2 * NPIX;      // [1,1,H,W]

    k_weights<<<1, 64>>>(ra, rl);
    k1_fused<<<dim3(W_IMG / TW, H_IMG / TH), 256>>>(raw, scatmap);

    // 1024 column-pairs x 128 strips = 131072 threads = 512 blocks of 256
    k2_vconv<<<512, 256>>>(bmode, env);
}